// round 1
// baseline (speedup 1.0000x reference)
#include <cuda_runtime.h>
#include <cuda_bf16.h>

#define N_NODES   50000
#define N_EDGES   640000
#define F_IN      64
#define EDGE_DIM  16
#define HID       128
#define NUM_GRAPHS 64
#define N_CLASSES 2
#define BN_EPS    1e-5f

// ---------------- scratch (device globals: no allocation allowed) ----------------
__device__ float g_h[N_NODES * HID];     // node features (current layer input)
__device__ float g_agg[N_NODES * HID];   // scatter-add accumulator
__device__ float g_z[N_NODES * HID];     // MLP output pre-BN
__device__ float g_stats[2 * HID];       // sum / sumsq  -> scale / shift
__device__ float g_pool[NUM_GRAPHS * HID];

// ---------------- zero kernels ----------------
__global__ void zero_agg_kernel() {
    int i = blockIdx.x * blockDim.x + threadIdx.x;
    int stride = gridDim.x * blockDim.x;
    float4 z = {0.f, 0.f, 0.f, 0.f};
    float4* p = (float4*)g_agg;
    for (; i < N_NODES * HID / 4; i += stride) p[i] = z;
}

__global__ void zero_stats_kernel() {
    int i = threadIdx.x;
    if (i < 2 * HID) g_stats[i] = 0.f;
}

__global__ void zero_pool_kernel() {
    int i = blockIdx.x * blockDim.x + threadIdx.x;
    if (i < NUM_GRAPHS * HID) g_pool[i] = 0.f;
}

// ---------------- encoder: h = x @ enc_W + enc_b   [50000,64]@[64,128] ----------------
// block: 256 threads, 128 rows; smem: W (64x128 = 32KB) + A (128x64 = 32KB)
__global__ void enc_kernel(const float* __restrict__ x,
                           const float* __restrict__ W,
                           const float* __restrict__ b) {
    extern __shared__ float sm[];
    float* sW = sm;               // [64][128]
    float* sA = sm + F_IN * HID;  // [128][64]
    const int tid = threadIdx.x;
    const int row0 = blockIdx.x * 128;

    for (int i = tid; i < F_IN * HID / 4; i += 256)
        ((float4*)sW)[i] = ((const float4*)W)[i];
    for (int i = tid; i < 128 * F_IN / 4; i += 256) {
        int r  = i >> 4;          // F_IN/4 = 16 float4 per row
        int k4 = i & 15;
        int grow = row0 + r;
        float4 v = {0.f, 0.f, 0.f, 0.f};
        if (grow < N_NODES) v = ((const float4*)x)[grow * 16 + k4];
        ((float4*)sA)[i] = v;
    }
    __syncthreads();

    const int col_g = tid & 15;
    const int row_g = tid >> 4;
    const int c0 = col_g * 8;

    float acc[8][8];
    {
        float4 b0 = *(const float4*)&b[c0];
        float4 b1 = *(const float4*)&b[c0 + 4];
#pragma unroll
        for (int i = 0; i < 8; i++) {
            acc[i][0] = b0.x; acc[i][1] = b0.y; acc[i][2] = b0.z; acc[i][3] = b0.w;
            acc[i][4] = b1.x; acc[i][5] = b1.y; acc[i][6] = b1.z; acc[i][7] = b1.w;
        }
    }
#pragma unroll 4
    for (int k = 0; k < F_IN; k++) {
        float a[8];
#pragma unroll
        for (int i = 0; i < 8; i++) a[i] = sA[(row_g * 8 + i) * F_IN + k];
        float4 w0 = *(const float4*)&sW[k * HID + c0];
        float4 w1 = *(const float4*)&sW[k * HID + c0 + 4];
#pragma unroll
        for (int i = 0; i < 8; i++) {
            acc[i][0] = fmaf(a[i], w0.x, acc[i][0]);
            acc[i][1] = fmaf(a[i], w0.y, acc[i][1]);
            acc[i][2] = fmaf(a[i], w0.z, acc[i][2]);
            acc[i][3] = fmaf(a[i], w0.w, acc[i][3]);
            acc[i][4] = fmaf(a[i], w1.x, acc[i][4]);
            acc[i][5] = fmaf(a[i], w1.y, acc[i][5]);
            acc[i][6] = fmaf(a[i], w1.z, acc[i][6]);
            acc[i][7] = fmaf(a[i], w1.w, acc[i][7]);
        }
    }
#pragma unroll
    for (int i = 0; i < 8; i++) {
        int grow = row0 + row_g * 8 + i;
        if (grow < N_NODES) {
            float4 o0 = {acc[i][0], acc[i][1], acc[i][2], acc[i][3]};
            float4 o1 = {acc[i][4], acc[i][5], acc[i][6], acc[i][7]};
            *(float4*)&g_h[grow * HID + c0]     = o0;
            *(float4*)&g_h[grow * HID + c0 + 4] = o1;
        }
    }
}

// ---------------- edge kernel: msg = relu(h[src] + ea@W + b); agg[dst] += msg ----------------
// one warp per edge; lane owns 4 channels; W (16x128) held in registers per lane
__global__ void edge_kernel(const int* __restrict__ ei,
                            const float* __restrict__ ea,
                            const float* __restrict__ W,
                            const float* __restrict__ b) {
    const int lane = threadIdx.x & 31;
    const int gw = (blockIdx.x * blockDim.x + threadIdx.x) >> 5;
    const int nw = (gridDim.x * blockDim.x) >> 5;
    const int c0 = lane * 4;

    float4 w[EDGE_DIM];
#pragma unroll
    for (int k = 0; k < EDGE_DIM; k++) w[k] = *(const float4*)&W[k * HID + c0];
    const float4 bias = *(const float4*)&b[c0];

    for (int e = gw; e < N_EDGES; e += nw) {
        int s = ei[e];
        int d = ei[N_EDGES + e];
        float eav = 0.f;
        if (lane < EDGE_DIM) eav = __ldg(&ea[e * EDGE_DIM + lane]);

        float4 acc = bias;
#pragma unroll
        for (int k = 0; k < EDGE_DIM; k++) {
            float a = __shfl_sync(0xffffffffu, eav, k);
            acc.x = fmaf(a, w[k].x, acc.x);
            acc.y = fmaf(a, w[k].y, acc.y);
            acc.z = fmaf(a, w[k].z, acc.z);
            acc.w = fmaf(a, w[k].w, acc.w);
        }
        const float4 hv = *(const float4*)&g_h[(long)s * HID + c0];
        float4 m;
        m.x = fmaxf(hv.x + acc.x, 0.f);
        m.y = fmaxf(hv.y + acc.y, 0.f);
        m.z = fmaxf(hv.z + acc.z, 0.f);
        m.w = fmaxf(hv.w + acc.w, 0.f);
        float* ap = &g_agg[(long)d * HID + c0];
        atomicAdd(ap + 0, m.x);
        atomicAdd(ap + 1, m.y);
        atomicAdd(ap + 2, m.z);
        atomicAdd(ap + 3, m.w);
    }
}

// ---------------- fused node MLP: z = relu((h+agg)@W1+b1)@W2 + b2 ----------------
// block: 256 threads, 128 rows; smem: W1 64KB + W2 64KB + A/T 64KB = 192KB
__global__ void mlp_kernel(const float* __restrict__ W1, const float* __restrict__ b1,
                           const float* __restrict__ W2, const float* __restrict__ b2) {
    extern __shared__ float sm[];
    float* sW1 = sm;
    float* sW2 = sm + HID * HID;
    float* sA  = sm + 2 * HID * HID;   // [128][128], reused for T
    const int tid = threadIdx.x;
    const int row0 = blockIdx.x * 128;

    for (int i = tid; i < HID * HID / 4; i += 256) {
        ((float4*)sW1)[i] = ((const float4*)W1)[i];
        ((float4*)sW2)[i] = ((const float4*)W2)[i];
    }
    for (int i = tid; i < 128 * HID / 4; i += 256) {
        int r  = i >> 5;   // HID/4 = 32 float4 per row
        int k4 = i & 31;
        int grow = row0 + r;
        float4 v = {0.f, 0.f, 0.f, 0.f};
        if (grow < N_NODES) {
            float4 hv = ((const float4*)g_h)[grow * 32 + k4];
            float4 av = ((const float4*)g_agg)[grow * 32 + k4];
            v.x = hv.x + av.x; v.y = hv.y + av.y; v.z = hv.z + av.z; v.w = hv.w + av.w;
        }
        ((float4*)sA)[i] = v;
    }
    __syncthreads();

    const int col_g = tid & 15;
    const int row_g = tid >> 4;
    const int c0 = col_g * 8;
    float acc[8][8];

    // ---- GEMM1 ----
    {
        float4 b0 = *(const float4*)&b1[c0];
        float4 b1v = *(const float4*)&b1[c0 + 4];
#pragma unroll
        for (int i = 0; i < 8; i++) {
            acc[i][0] = b0.x; acc[i][1] = b0.y; acc[i][2] = b0.z; acc[i][3] = b0.w;
            acc[i][4] = b1v.x; acc[i][5] = b1v.y; acc[i][6] = b1v.z; acc[i][7] = b1v.w;
        }
    }
#pragma unroll 4
    for (int k = 0; k < HID; k++) {
        float a[8];
#pragma unroll
        for (int i = 0; i < 8; i++) a[i] = sA[(row_g * 8 + i) * HID + k];
        float4 w0 = *(const float4*)&sW1[k * HID + c0];
        float4 w1 = *(const float4*)&sW1[k * HID + c0 + 4];
#pragma unroll
        for (int i = 0; i < 8; i++) {
            acc[i][0] = fmaf(a[i], w0.x, acc[i][0]);
            acc[i][1] = fmaf(a[i], w0.y, acc[i][1]);
            acc[i][2] = fmaf(a[i], w0.z, acc[i][2]);
            acc[i][3] = fmaf(a[i], w0.w, acc[i][3]);
            acc[i][4] = fmaf(a[i], w1.x, acc[i][4]);
            acc[i][5] = fmaf(a[i], w1.y, acc[i][5]);
            acc[i][6] = fmaf(a[i], w1.z, acc[i][6]);
            acc[i][7] = fmaf(a[i], w1.w, acc[i][7]);
        }
    }
    __syncthreads();   // everyone done reading A
    // write T = relu(acc) over sA
#pragma unroll
    for (int i = 0; i < 8; i++) {
        float4 o0 = {fmaxf(acc[i][0], 0.f), fmaxf(acc[i][1], 0.f),
                     fmaxf(acc[i][2], 0.f), fmaxf(acc[i][3], 0.f)};
        float4 o1 = {fmaxf(acc[i][4], 0.f), fmaxf(acc[i][5], 0.f),
                     fmaxf(acc[i][6], 0.f), fmaxf(acc[i][7], 0.f)};
        *(float4*)&sA[(row_g * 8 + i) * HID + c0]     = o0;
        *(float4*)&sA[(row_g * 8 + i) * HID + c0 + 4] = o1;
    }
    __syncthreads();

    // ---- GEMM2 ----
    {
        float4 b0 = *(const float4*)&b2[c0];
        float4 b1v = *(const float4*)&b2[c0 + 4];
#pragma unroll
        for (int i = 0; i < 8; i++) {
            acc[i][0] = b0.x; acc[i][1] = b0.y; acc[i][2] = b0.z; acc[i][3] = b0.w;
            acc[i][4] = b1v.x; acc[i][5] = b1v.y; acc[i][6] = b1v.z; acc[i][7] = b1v.w;
        }
    }
#pragma unroll 4
    for (int k = 0; k < HID; k++) {
        float a[8];
#pragma unroll
        for (int i = 0; i < 8; i++) a[i] = sA[(row_g * 8 + i) * HID + k];
        float4 w0 = *(const float4*)&sW2[k * HID + c0];
        float4 w1 = *(const float4*)&sW2[k * HID + c0 + 4];
#pragma unroll
        for (int i = 0; i < 8; i++) {
            acc[i][0] = fmaf(a[i], w0.x, acc[i][0]);
            acc[i][1] = fmaf(a[i], w0.y, acc[i][1]);
            acc[i][2] = fmaf(a[i], w0.z, acc[i][2]);
            acc[i][3] = fmaf(a[i], w0.w, acc[i][3]);
            acc[i][4] = fmaf(a[i], w1.x, acc[i][4]);
            acc[i][5] = fmaf(a[i], w1.y, acc[i][5]);
            acc[i][6] = fmaf(a[i], w1.z, acc[i][6]);
            acc[i][7] = fmaf(a[i], w1.w, acc[i][7]);
        }
    }
#pragma unroll
    for (int i = 0; i < 8; i++) {
        int grow = row0 + row_g * 8 + i;
        if (grow < N_NODES) {
            float4 o0 = {acc[i][0], acc[i][1], acc[i][2], acc[i][3]};
            float4 o1 = {acc[i][4], acc[i][5], acc[i][6], acc[i][7]};
            *(float4*)&g_z[grow * HID + c0]     = o0;
            *(float4*)&g_z[grow * HID + c0 + 4] = o1;
        }
    }
}

// ---------------- BN stats: per-channel sum, sumsq over g_z ----------------
__global__ void stats_kernel() {
    const int c = threadIdx.x;  // 128 threads
    float s = 0.f, sq = 0.f;
    for (int row = blockIdx.x; row < N_NODES; row += gridDim.x) {
        float v = g_z[row * HID + c];
        s += v;
        sq = fmaf(v, v, sq);
    }
    atomicAdd(&g_stats[c], s);
    atomicAdd(&g_stats[HID + c], sq);
}

__global__ void bn_finalize_kernel(const float* __restrict__ gamma,
                                   const float* __restrict__ beta) {
    const int c = threadIdx.x;  // 128 threads
    float s  = g_stats[c];
    float sq = g_stats[HID + c];
    const float inv_n = 1.f / (float)N_NODES;
    float mean = s * inv_n;
    float var  = sq * inv_n - mean * mean;
    float sc = gamma[c] * rsqrtf(var + BN_EPS);
    float sh = beta[c] - mean * sc;
    __syncthreads();
    g_stats[c] = sc;
    g_stats[HID + c] = sh;
}

// ---------------- BN apply + relu: h = relu(z*scale + shift) ----------------
__global__ void bn_apply_kernel() {
    int i = blockIdx.x * blockDim.x + threadIdx.x;
    int stride = gridDim.x * blockDim.x;
    for (; i < N_NODES * HID / 4; i += stride) {
        int c4 = (i & 31) * 4;  // channel of first component
        float4 z  = ((const float4*)g_z)[i];
        float4 sc = *(const float4*)&g_stats[c4];
        float4 sh = *(const float4*)&g_stats[HID + c4];
        float4 o;
        o.x = fmaxf(fmaf(z.x, sc.x, sh.x), 0.f);
        o.y = fmaxf(fmaf(z.y, sc.y, sh.y), 0.f);
        o.z = fmaxf(fmaf(z.z, sc.z, sh.z), 0.f);
        o.w = fmaxf(fmaf(z.w, sc.w, sh.w), 0.f);
        ((float4*)g_h)[i] = o;
    }
}

// ---------------- global_add_pool over sorted batch ----------------
__global__ void pool_kernel(const int* __restrict__ batch) {
    const int c = threadIdx.x;  // 128 threads
    const int row0 = blockIdx.x * 256;
    if (row0 >= N_NODES) return;
    const int rowEnd = min(row0 + 256, N_NODES);
    float acc = 0.f;
    int cur = batch[row0];
    for (int row = row0; row < rowEnd; row++) {
        int bv = batch[row];
        if (bv != cur) {
            atomicAdd(&g_pool[cur * HID + c], acc);
            acc = 0.f;
            cur = bv;
        }
        acc += g_h[row * HID + c];
    }
    atomicAdd(&g_pool[cur * HID + c], acc);
}

// ---------------- head: out = relu(g@W1+b1)@W2 + b2 ----------------
// single block, 256 threads; smem: G/T (64x128 = 32KB) + W1 (64KB)
__global__ void head_kernel(const float* __restrict__ W1, const float* __restrict__ b1,
                            const float* __restrict__ W2, const float* __restrict__ b2,
                            float* __restrict__ out) {
    extern __shared__ float sm[];
    float* sG = sm;                    // [64][128]
    float* sW = sm + NUM_GRAPHS * HID; // [128][128]
    const int tid = threadIdx.x;  // 256

    for (int i = tid; i < NUM_GRAPHS * HID / 4; i += 256)
        ((float4*)sG)[i] = ((const float4*)g_pool)[i];
    for (int i = tid; i < HID * HID / 4; i += 256)
        ((float4*)sW)[i] = ((const float4*)W1)[i];
    __syncthreads();

    const int c  = tid & 127;
    const int r0 = (tid >> 7) * 32;
    float t[32];
    float bc = b1[c];
#pragma unroll
    for (int i = 0; i < 32; i++) t[i] = bc;
    for (int k = 0; k < HID; k++) {
        float wv = sW[k * HID + c];
#pragma unroll 8
        for (int i = 0; i < 32; i++)
            t[i] = fmaf(sG[(r0 + i) * HID + k], wv, t[i]);
    }
    __syncthreads();
#pragma unroll
    for (int i = 0; i < 32; i++)
        sG[(r0 + i) * HID + c] = fmaxf(t[i], 0.f);
    __syncthreads();

    if (tid < NUM_GRAPHS * N_CLASSES) {
        int r  = tid / N_CLASSES;
        int cc = tid % N_CLASSES;
        float accv = b2[cc];
        for (int k = 0; k < HID; k++)
            accv = fmaf(sG[r * HID + k], W2[k * N_CLASSES + cc], accv);
        out[tid] = accv;
    }
}

// ---------------- launch ----------------
extern "C" void kernel_launch(void* const* d_in, const int* in_sizes, int n_in,
                              void* d_out, int out_size) {
    const float* x      = (const float*)d_in[0];
    const int*   ei     = (const int*)d_in[1];
    const float* ea     = (const float*)d_in[2];
    const int*   batch  = (const int*)d_in[3];
    const float* enc_W  = (const float*)d_in[4];
    const float* enc_b  = (const float*)d_in[5];
    const float* edge_W = (const float*)d_in[6];
    const float* edge_b = (const float*)d_in[7];
    const float* mlp_W1 = (const float*)d_in[8];
    const float* mlp_b1 = (const float*)d_in[9];
    const float* mlp_W2 = (const float*)d_in[10];
    const float* mlp_b2 = (const float*)d_in[11];
    const float* bn_g   = (const float*)d_in[12];
    const float* bn_b   = (const float*)d_in[13];
    const float* hW1    = (const float*)d_in[14];
    const float* hb1    = (const float*)d_in[15];
    const float* hW2    = (const float*)d_in[16];
    const float* hb2    = (const float*)d_in[17];
    float* out = (float*)d_out;

    cudaFuncSetAttribute(enc_kernel,  cudaFuncAttributeMaxDynamicSharedMemorySize, 64 * 1024);
    cudaFuncSetAttribute(mlp_kernel,  cudaFuncAttributeMaxDynamicSharedMemorySize, 192 * 1024);
    cudaFuncSetAttribute(head_kernel, cudaFuncAttributeMaxDynamicSharedMemorySize, 96 * 1024);

    const int row_blocks = (N_NODES + 127) / 128;  // 391

    enc_kernel<<<row_blocks, 256, 64 * 1024>>>(x, enc_W, enc_b);

    for (int l = 0; l < 3; l++) {
        zero_agg_kernel<<<2048, 256>>>();
        edge_kernel<<<1184, 128>>>(ei, ea,
                                   edge_W + (size_t)l * EDGE_DIM * HID,
                                   edge_b + (size_t)l * HID);
        mlp_kernel<<<row_blocks, 256, 192 * 1024>>>(
            mlp_W1 + (size_t)l * HID * HID, mlp_b1 + (size_t)l * HID,
            mlp_W2 + (size_t)l * HID * HID, mlp_b2 + (size_t)l * HID);
        zero_stats_kernel<<<1, 256>>>();
        stats_kernel<<<512, 128>>>();
        bn_finalize_kernel<<<1, 128>>>(bn_g + (size_t)l * HID, bn_b + (size_t)l * HID);
        bn_apply_kernel<<<2048, 256>>>();
    }

    zero_pool_kernel<<<32, 256>>>();
    pool_kernel<<<(N_NODES + 255) / 256, 128>>>(batch);
    head_kernel<<<1, 256, 96 * 1024>>>(hW1, hb1, hW2, hb2, out);
}

// round 2
// speedup vs baseline: 1.0745x; 1.0745x over previous
#include <cuda_runtime.h>
#include <cuda_bf16.h>

#define N_NODES   50000
#define N_EDGES   640000
#define F_IN      64
#define EDGE_DIM  16
#define HID       128
#define N_LAYERS  3
#define NUM_GRAPHS 64
#define N_CLASSES 2
#define BN_EPS    1e-5f

// ---------------- scratch ----------------
__device__ float g_h[N_NODES * HID];
__device__ float g_agg[N_NODES * HID];
__device__ float g_z[N_NODES * HID];
__device__ float g_stats[N_LAYERS * 2 * HID];   // per-layer sum[128], sumsq[128]
__device__ float g_pool[NUM_GRAPHS * HID];

// ---------------- init: zero agg, stats, pool ----------------
__global__ void zero_init_kernel() {
    int i = blockIdx.x * blockDim.x + threadIdx.x;
    int stride = gridDim.x * blockDim.x;
    float4 z = {0.f, 0.f, 0.f, 0.f};
    float4* p = (float4*)g_agg;
    for (int j = i; j < N_NODES * HID / 4; j += stride) p[j] = z;
    if (i < N_LAYERS * 2 * HID) g_stats[i] = 0.f;
    if (i < NUM_GRAPHS * HID) g_pool[i] = 0.f;
}

// ---------------- encoder: h = x @ enc_W + enc_b ----------------
__global__ void enc_kernel(const float* __restrict__ x,
                           const float* __restrict__ W,
                           const float* __restrict__ b) {
    extern __shared__ float sm[];
    float* sW = sm;               // [64][128]
    float* sA = sm + F_IN * HID;  // [128][64]
    const int tid = threadIdx.x;
    const int row0 = blockIdx.x * 128;

    for (int i = tid; i < F_IN * HID / 4; i += 256)
        ((float4*)sW)[i] = ((const float4*)W)[i];
    for (int i = tid; i < 128 * F_IN / 4; i += 256) {
        int r  = i >> 4;
        int k4 = i & 15;
        int grow = row0 + r;
        float4 v = {0.f, 0.f, 0.f, 0.f};
        if (grow < N_NODES) v = ((const float4*)x)[grow * 16 + k4];
        ((float4*)sA)[i] = v;
    }
    __syncthreads();

    const int col_g = tid & 15;
    const int row_g = tid >> 4;
    const int c0 = col_g * 8;

    float acc[8][8];
    {
        float4 b0 = *(const float4*)&b[c0];
        float4 b1 = *(const float4*)&b[c0 + 4];
#pragma unroll
        for (int i = 0; i < 8; i++) {
            acc[i][0] = b0.x; acc[i][1] = b0.y; acc[i][2] = b0.z; acc[i][3] = b0.w;
            acc[i][4] = b1.x; acc[i][5] = b1.y; acc[i][6] = b1.z; acc[i][7] = b1.w;
        }
    }
#pragma unroll 4
    for (int k = 0; k < F_IN; k++) {
        float a[8];
#pragma unroll
        for (int i = 0; i < 8; i++) a[i] = sA[(row_g * 8 + i) * F_IN + k];
        float4 w0 = *(const float4*)&sW[k * HID + c0];
        float4 w1 = *(const float4*)&sW[k * HID + c0 + 4];
#pragma unroll
        for (int i = 0; i < 8; i++) {
            acc[i][0] = fmaf(a[i], w0.x, acc[i][0]);
            acc[i][1] = fmaf(a[i], w0.y, acc[i][1]);
            acc[i][2] = fmaf(a[i], w0.z, acc[i][2]);
            acc[i][3] = fmaf(a[i], w0.w, acc[i][3]);
            acc[i][4] = fmaf(a[i], w1.x, acc[i][4]);
            acc[i][5] = fmaf(a[i], w1.y, acc[i][5]);
            acc[i][6] = fmaf(a[i], w1.z, acc[i][6]);
            acc[i][7] = fmaf(a[i], w1.w, acc[i][7]);
        }
    }
#pragma unroll
    for (int i = 0; i < 8; i++) {
        int grow = row0 + row_g * 8 + i;
        if (grow < N_NODES) {
            float4 o0 = {acc[i][0], acc[i][1], acc[i][2], acc[i][3]};
            float4 o1 = {acc[i][4], acc[i][5], acc[i][6], acc[i][7]};
            *(float4*)&g_h[grow * HID + c0]     = o0;
            *(float4*)&g_h[grow * HID + c0 + 4] = o1;
        }
    }
}

// ---------------- edge kernel: msg = relu(h[src] + ea@W + b); agg[dst] += msg ----------------
// one warp per edge; lane owns 4 channels; vector RED (16B) per lane
__global__ void edge_kernel(const int* __restrict__ ei,
                            const float* __restrict__ ea,
                            const float* __restrict__ W,
                            const float* __restrict__ b) {
    const int lane = threadIdx.x & 31;
    const int gw = (blockIdx.x * blockDim.x + threadIdx.x) >> 5;
    const int nw = (gridDim.x * blockDim.x) >> 5;
    const int c0 = lane * 4;

    float4 w[EDGE_DIM];
#pragma unroll
    for (int k = 0; k < EDGE_DIM; k++) w[k] = *(const float4*)&W[k * HID + c0];
    const float4 bias = *(const float4*)&b[c0];

    for (int e = gw; e < N_EDGES; e += nw) {
        int s = ei[e];
        int d = ei[N_EDGES + e];
        float eav = 0.f;
        if (lane < EDGE_DIM) eav = __ldg(&ea[e * EDGE_DIM + lane]);

        float4 acc = bias;
#pragma unroll
        for (int k = 0; k < EDGE_DIM; k++) {
            float a = __shfl_sync(0xffffffffu, eav, k);
            acc.x = fmaf(a, w[k].x, acc.x);
            acc.y = fmaf(a, w[k].y, acc.y);
            acc.z = fmaf(a, w[k].z, acc.z);
            acc.w = fmaf(a, w[k].w, acc.w);
        }
        const float4 hv = *(const float4*)&g_h[(long)s * HID + c0];
        float mx = fmaxf(hv.x + acc.x, 0.f);
        float my = fmaxf(hv.y + acc.y, 0.f);
        float mz = fmaxf(hv.z + acc.z, 0.f);
        float mw = fmaxf(hv.w + acc.w, 0.f);
        float* ap = &g_agg[(long)d * HID + c0];
        asm volatile("red.global.add.v4.f32 [%0], {%1, %2, %3, %4};"
                     :: "l"(ap), "f"(mx), "f"(my), "f"(mz), "f"(mw)
                     : "memory");
    }
}

// ---------------- fused node MLP + BN-stats epilogue ----------------
// 512 threads, 128 rows/block; smem: W1 64KB + W2 64KB + A/T 64KB = 192KB
__global__ void mlp_kernel(const float* __restrict__ W1, const float* __restrict__ b1,
                           const float* __restrict__ W2, const float* __restrict__ b2,
                           int layer) {
    extern __shared__ float sm[];
    float* sW1 = sm;                   // reused for stats after GEMM1
    float* sW2 = sm + HID * HID;
    float* sA  = sm + 2 * HID * HID;   // [128][128], reused for T
    const int tid = threadIdx.x;       // 512
    const int row0 = blockIdx.x * 128;

    for (int i = tid; i < HID * HID / 4; i += 512) {
        ((float4*)sW1)[i] = ((const float4*)W1)[i];
        ((float4*)sW2)[i] = ((const float4*)W2)[i];
    }
    for (int i = tid; i < 128 * HID / 4; i += 512) {
        int r  = i >> 5;
        int k4 = i & 31;
        int grow = row0 + r;
        float4 v = {0.f, 0.f, 0.f, 0.f};
        if (grow < N_NODES) {
            float4 hv = ((const float4*)g_h)[grow * 32 + k4];
            float4 av = ((const float4*)g_agg)[grow * 32 + k4];
            v.x = hv.x + av.x; v.y = hv.y + av.y; v.z = hv.z + av.z; v.w = hv.w + av.w;
        }
        ((float4*)sA)[i] = v;
    }
    __syncthreads();

    const int col_g = tid & 15;
    const int row_g = tid >> 4;        // 0..31, 4 rows each
    const int c0 = col_g * 8;
    const int r0 = row_g * 4;
    float acc[4][8];

    // ---- GEMM1 ----
    {
        float4 b0 = *(const float4*)&b1[c0];
        float4 b1v = *(const float4*)&b1[c0 + 4];
#pragma unroll
        for (int i = 0; i < 4; i++) {
            acc[i][0] = b0.x; acc[i][1] = b0.y; acc[i][2] = b0.z; acc[i][3] = b0.w;
            acc[i][4] = b1v.x; acc[i][5] = b1v.y; acc[i][6] = b1v.z; acc[i][7] = b1v.w;
        }
    }
#pragma unroll 4
    for (int k = 0; k < HID; k++) {
        float a[4];
#pragma unroll
        for (int i = 0; i < 4; i++) a[i] = sA[(r0 + i) * HID + k];
        float4 w0 = *(const float4*)&sW1[k * HID + c0];
        float4 w1 = *(const float4*)&sW1[k * HID + c0 + 4];
#pragma unroll
        for (int i = 0; i < 4; i++) {
            acc[i][0] = fmaf(a[i], w0.x, acc[i][0]);
            acc[i][1] = fmaf(a[i], w0.y, acc[i][1]);
            acc[i][2] = fmaf(a[i], w0.z, acc[i][2]);
            acc[i][3] = fmaf(a[i], w0.w, acc[i][3]);
            acc[i][4] = fmaf(a[i], w1.x, acc[i][4]);
            acc[i][5] = fmaf(a[i], w1.y, acc[i][5]);
            acc[i][6] = fmaf(a[i], w1.z, acc[i][6]);
            acc[i][7] = fmaf(a[i], w1.w, acc[i][7]);
        }
    }
    __syncthreads();   // everyone done reading sA and sW1
    // write T = relu(acc) into sA; zero stats region in sW1
#pragma unroll
    for (int i = 0; i < 4; i++) {
        float4 o0 = {fmaxf(acc[i][0], 0.f), fmaxf(acc[i][1], 0.f),
                     fmaxf(acc[i][2], 0.f), fmaxf(acc[i][3], 0.f)};
        float4 o1 = {fmaxf(acc[i][4], 0.f), fmaxf(acc[i][5], 0.f),
                     fmaxf(acc[i][6], 0.f), fmaxf(acc[i][7], 0.f)};
        *(float4*)&sA[(r0 + i) * HID + c0]     = o0;
        *(float4*)&sA[(r0 + i) * HID + c0 + 4] = o1;
    }
    if (tid < 2 * HID) sW1[tid] = 0.f;   // ssum[128] | ssq[128]
    __syncthreads();

    // ---- GEMM2 ----
    {
        float4 b0 = *(const float4*)&b2[c0];
        float4 b1v = *(const float4*)&b2[c0 + 4];
#pragma unroll
        for (int i = 0; i < 4; i++) {
            acc[i][0] = b0.x; acc[i][1] = b0.y; acc[i][2] = b0.z; acc[i][3] = b0.w;
            acc[i][4] = b1v.x; acc[i][5] = b1v.y; acc[i][6] = b1v.z; acc[i][7] = b1v.w;
        }
    }
#pragma unroll 4
    for (int k = 0; k < HID; k++) {
        float a[4];
#pragma unroll
        for (int i = 0; i < 4; i++) a[i] = sA[(r0 + i) * HID + k];
        float4 w0 = *(const float4*)&sW2[k * HID + c0];
        float4 w1 = *(const float4*)&sW2[k * HID + c0 + 4];
#pragma unroll
        for (int i = 0; i < 4; i++) {
            acc[i][0] = fmaf(a[i], w0.x, acc[i][0]);
            acc[i][1] = fmaf(a[i], w0.y, acc[i][1]);
            acc[i][2] = fmaf(a[i], w0.z, acc[i][2]);
            acc[i][3] = fmaf(a[i], w0.w, acc[i][3]);
            acc[i][4] = fmaf(a[i], w1.x, acc[i][4]);
            acc[i][5] = fmaf(a[i], w1.y, acc[i][5]);
            acc[i][6] = fmaf(a[i], w1.z, acc[i][6]);
            acc[i][7] = fmaf(a[i], w1.w, acc[i][7]);
        }
    }
    // write z + accumulate per-block BN stats
    float s[8], sq[8];
#pragma unroll
    for (int j = 0; j < 8; j++) { s[j] = 0.f; sq[j] = 0.f; }
#pragma unroll
    for (int i = 0; i < 4; i++) {
        int grow = row0 + r0 + i;
        if (grow < N_NODES) {
            float4 o0 = {acc[i][0], acc[i][1], acc[i][2], acc[i][3]};
            float4 o1 = {acc[i][4], acc[i][5], acc[i][6], acc[i][7]};
            *(float4*)&g_z[grow * HID + c0]     = o0;
            *(float4*)&g_z[grow * HID + c0 + 4] = o1;
#pragma unroll
            for (int j = 0; j < 8; j++) {
                s[j] += acc[i][j];
                sq[j] = fmaf(acc[i][j], acc[i][j], sq[j]);
            }
        }
    }
#pragma unroll
    for (int j = 0; j < 8; j++) {
        atomicAdd(&sW1[c0 + j], s[j]);
        atomicAdd(&sW1[HID + c0 + j], sq[j]);
    }
    __syncthreads();
    if (tid < 2 * HID)
        atomicAdd(&g_stats[layer * 2 * HID + tid], sW1[tid]);
}

// ---------------- BN apply + relu + zero agg for next layer ----------------
__global__ void bn_apply_kernel(const float* __restrict__ gamma,
                                const float* __restrict__ beta,
                                int layer) {
    const int i0 = blockIdx.x * blockDim.x + threadIdx.x;
    const int stride = gridDim.x * blockDim.x;   // multiple of 32
    const int c4 = (i0 & 31) * 4;                // constant per thread
    const float* st = &g_stats[layer * 2 * HID];
    const float inv_n = 1.f / (float)N_NODES;
    float sc[4], sh[4];
#pragma unroll
    for (int j = 0; j < 4; j++) {
        float mean = st[c4 + j] * inv_n;
        float var  = st[HID + c4 + j] * inv_n - mean * mean;
        sc[j] = gamma[c4 + j] * rsqrtf(var + BN_EPS);
        sh[j] = beta[c4 + j] - mean * sc[j];
    }
    float4 zero = {0.f, 0.f, 0.f, 0.f};
    for (int i = i0; i < N_NODES * HID / 4; i += stride) {
        float4 z = ((const float4*)g_z)[i];
        float4 o;
        o.x = fmaxf(fmaf(z.x, sc[0], sh[0]), 0.f);
        o.y = fmaxf(fmaf(z.y, sc[1], sh[1]), 0.f);
        o.z = fmaxf(fmaf(z.z, sc[2], sh[2]), 0.f);
        o.w = fmaxf(fmaf(z.w, sc[3], sh[3]), 0.f);
        ((float4*)g_h)[i] = o;
        ((float4*)g_agg)[i] = zero;   // ready for next layer's scatter
    }
}

// ---------------- global_add_pool over sorted batch ----------------
__global__ void pool_kernel(const int* __restrict__ batch) {
    const int c = threadIdx.x;  // 128
    const int row0 = blockIdx.x * 256;
    if (row0 >= N_NODES) return;
    const int rowEnd = min(row0 + 256, N_NODES);
    float acc = 0.f;
    int cur = batch[row0];
    for (int row = row0; row < rowEnd; row++) {
        int bv = batch[row];
        if (bv != cur) {
            atomicAdd(&g_pool[cur * HID + c], acc);
            acc = 0.f;
            cur = bv;
        }
        acc += g_h[row * HID + c];
    }
    atomicAdd(&g_pool[cur * HID + c], acc);
}

// ---------------- head ----------------
__global__ void head_kernel(const float* __restrict__ W1, const float* __restrict__ b1,
                            const float* __restrict__ W2, const float* __restrict__ b2,
                            float* __restrict__ out) {
    extern __shared__ float sm[];
    float* sG = sm;                    // [64][128]
    float* sW = sm + NUM_GRAPHS * HID; // [128][128]
    const int tid = threadIdx.x;  // 256

    for (int i = tid; i < NUM_GRAPHS * HID / 4; i += 256)
        ((float4*)sG)[i] = ((const float4*)g_pool)[i];
    for (int i = tid; i < HID * HID / 4; i += 256)
        ((float4*)sW)[i] = ((const float4*)W1)[i];
    __syncthreads();

    const int c  = tid & 127;
    const int r0 = (tid >> 7) * 32;
    float t[32];
    float bc = b1[c];
#pragma unroll
    for (int i = 0; i < 32; i++) t[i] = bc;
    for (int k = 0; k < HID; k++) {
        float wv = sW[k * HID + c];
#pragma unroll 8
        for (int i = 0; i < 32; i++)
            t[i] = fmaf(sG[(r0 + i) * HID + k], wv, t[i]);
    }
    __syncthreads();
#pragma unroll
    for (int i = 0; i < 32; i++)
        sG[(r0 + i) * HID + c] = fmaxf(t[i], 0.f);
    __syncthreads();

    if (tid < NUM_GRAPHS * N_CLASSES) {
        int r  = tid / N_CLASSES;
        int cc = tid % N_CLASSES;
        float accv = b2[cc];
        for (int k = 0; k < HID; k++)
            accv = fmaf(sG[r * HID + k], W2[k * N_CLASSES + cc], accv);
        out[tid] = accv;
    }
}

// ---------------- launch ----------------
extern "C" void kernel_launch(void* const* d_in, const int* in_sizes, int n_in,
                              void* d_out, int out_size) {
    const float* x      = (const float*)d_in[0];
    const int*   ei     = (const int*)d_in[1];
    const float* ea     = (const float*)d_in[2];
    const int*   batch  = (const int*)d_in[3];
    const float* enc_W  = (const float*)d_in[4];
    const float* enc_b  = (const float*)d_in[5];
    const float* edge_W = (const float*)d_in[6];
    const float* edge_b = (const float*)d_in[7];
    const float* mlp_W1 = (const float*)d_in[8];
    const float* mlp_b1 = (const float*)d_in[9];
    const float* mlp_W2 = (const float*)d_in[10];
    const float* mlp_b2 = (const float*)d_in[11];
    const float* bn_g   = (const float*)d_in[12];
    const float* bn_b   = (const float*)d_in[13];
    const float* hW1    = (const float*)d_in[14];
    const float* hb1    = (const float*)d_in[15];
    const float* hW2    = (const float*)d_in[16];
    const float* hb2    = (const float*)d_in[17];
    float* out = (float*)d_out;

    cudaFuncSetAttribute(enc_kernel,  cudaFuncAttributeMaxDynamicSharedMemorySize, 64 * 1024);
    cudaFuncSetAttribute(mlp_kernel,  cudaFuncAttributeMaxDynamicSharedMemorySize, 192 * 1024);
    cudaFuncSetAttribute(head_kernel, cudaFuncAttributeMaxDynamicSharedMemorySize, 96 * 1024);

    const int row_blocks = (N_NODES + 127) / 128;  // 391

    zero_init_kernel<<<2048, 256>>>();
    enc_kernel<<<row_blocks, 256, 64 * 1024>>>(x, enc_W, enc_b);

    for (int l = 0; l < N_LAYERS; l++) {
        edge_kernel<<<1184, 128>>>(ei, ea,
                                   edge_W + (size_t)l * EDGE_DIM * HID,
                                   edge_b + (size_t)l * HID);
        mlp_kernel<<<row_blocks, 512, 192 * 1024>>>(
            mlp_W1 + (size_t)l * HID * HID, mlp_b1 + (size_t)l * HID,
            mlp_W2 + (size_t)l * HID * HID, mlp_b2 + (size_t)l * HID, l);
        bn_apply_kernel<<<2048, 256>>>(bn_g + (size_t)l * HID,
                                       bn_b + (size_t)l * HID, l);
    }

    pool_kernel<<<(N_NODES + 255) / 256, 128>>>(batch);
    head_kernel<<<1, 256, 96 * 1024>>>(hW1, hb1, hW2, hb2, out);
}

// round 3
// speedup vs baseline: 1.1680x; 1.0870x over previous
#include <cuda_runtime.h>
#include <cuda_bf16.h>

#define N_NODES   50000
#define N_EDGES   640000
#define F_IN      64
#define EDGE_DIM  16
#define HID       128
#define N_LAYERS  3
#define NUM_GRAPHS 64
#define N_CLASSES 2
#define BN_EPS    1e-5f
#define FULLMASK  0xffffffffu

// ---------------- scratch ----------------
__device__ float g_h[N_NODES * HID];      // node features (post-BN)
__device__ float g_zin[N_NODES * HID];    // h + aggregated messages (MLP input)
__device__ float g_z[N_NODES * HID];      // MLP output pre-BN
__device__ float g_stats[N_LAYERS * 2 * HID];
__device__ float g_pool[NUM_GRAPHS * HID];
__device__ int   g_deg[N_NODES];          // histogram
__device__ int   g_off[N_NODES + 1];      // CSR offsets
__device__ int   g_pos[N_NODES];          // scatter cursors
__device__ int2  g_csr[N_EDGES];          // (src, edge_id) sorted by dst

// ---------------- init ----------------
__global__ void zero_init_kernel() {
    int i = blockIdx.x * blockDim.x + threadIdx.x;
    int stride = gridDim.x * blockDim.x;
    for (int j = i; j < N_NODES; j += stride) g_deg[j] = 0;
    if (i < N_LAYERS * 2 * HID) g_stats[i] = 0.f;
    if (i < NUM_GRAPHS * HID) g_pool[i] = 0.f;
}

// ---------------- CSR build ----------------
__global__ void csr_hist_kernel(const int* __restrict__ ei) {
    int e = blockIdx.x * blockDim.x + threadIdx.x;
    if (e < N_EDGES) atomicAdd(&g_deg[ei[N_EDGES + e]], 1);
}

__global__ void csr_scan_kernel() {   // 1 block, 1024 threads
    __shared__ int part[1024];
    const int T = 1024;
    const int C = (N_NODES + T - 1) / T;  // 49
    int t = threadIdx.x;
    int lo = t * C, hi = min(lo + C, N_NODES);
    int s = 0;
    for (int i = lo; i < hi; i++) s += g_deg[i];
    part[t] = s;
    __syncthreads();
    for (int d = 1; d < T; d <<= 1) {
        int v = (t >= d) ? part[t - d] : 0;
        __syncthreads();
        part[t] += v;
        __syncthreads();
    }
    int run = (t > 0) ? part[t - 1] : 0;
    for (int i = lo; i < hi; i++) {
        g_off[i] = run;
        g_pos[i] = run;
        run += g_deg[i];
    }
    if (t == T - 1) g_off[N_NODES] = run;
}

__global__ void csr_scatter_kernel(const int* __restrict__ ei) {
    int e = blockIdx.x * blockDim.x + threadIdx.x;
    if (e < N_EDGES) {
        int s = ei[e];
        int d = ei[N_EDGES + e];
        int p = atomicAdd(&g_pos[d], 1);
        g_csr[p] = make_int2(s, e);
    }
}

// ---------------- encoder: h = x @ enc_W + enc_b ----------------
__global__ void enc_kernel(const float* __restrict__ x,
                           const float* __restrict__ W,
                           const float* __restrict__ b) {
    extern __shared__ float sm[];
    float* sW = sm;               // [64][128]
    float* sA = sm + F_IN * HID;  // [128][64]
    const int tid = threadIdx.x;
    const int row0 = blockIdx.x * 128;

    for (int i = tid; i < F_IN * HID / 4; i += 256)
        ((float4*)sW)[i] = ((const float4*)W)[i];
    for (int i = tid; i < 128 * F_IN / 4; i += 256) {
        int r  = i >> 4;
        int k4 = i & 15;
        int grow = row0 + r;
        float4 v = {0.f, 0.f, 0.f, 0.f};
        if (grow < N_NODES) v = ((const float4*)x)[grow * 16 + k4];
        ((float4*)sA)[i] = v;
    }
    __syncthreads();

    const int col_g = tid & 15;
    const int row_g = tid >> 4;
    const int c0 = col_g * 8;

    float acc[8][8];
    {
        float4 b0 = *(const float4*)&b[c0];
        float4 b1 = *(const float4*)&b[c0 + 4];
#pragma unroll
        for (int i = 0; i < 8; i++) {
            acc[i][0] = b0.x; acc[i][1] = b0.y; acc[i][2] = b0.z; acc[i][3] = b0.w;
            acc[i][4] = b1.x; acc[i][5] = b1.y; acc[i][6] = b1.z; acc[i][7] = b1.w;
        }
    }
#pragma unroll 1
    for (int k0 = 0; k0 < F_IN; k0 += 4) {
        float4 av[8];
#pragma unroll
        for (int i = 0; i < 8; i++)
            av[i] = *(const float4*)&sA[(row_g * 8 + i) * F_IN + k0];
#pragma unroll
        for (int kk = 0; kk < 4; kk++) {
            float4 w0 = *(const float4*)&sW[(k0 + kk) * HID + c0];
            float4 w1 = *(const float4*)&sW[(k0 + kk) * HID + c0 + 4];
#pragma unroll
            for (int i = 0; i < 8; i++) {
                float a = ((const float*)&av[i])[kk];
                acc[i][0] = fmaf(a, w0.x, acc[i][0]);
                acc[i][1] = fmaf(a, w0.y, acc[i][1]);
                acc[i][2] = fmaf(a, w0.z, acc[i][2]);
                acc[i][3] = fmaf(a, w0.w, acc[i][3]);
                acc[i][4] = fmaf(a, w1.x, acc[i][4]);
                acc[i][5] = fmaf(a, w1.y, acc[i][5]);
                acc[i][6] = fmaf(a, w1.z, acc[i][6]);
                acc[i][7] = fmaf(a, w1.w, acc[i][7]);
            }
        }
    }
#pragma unroll
    for (int i = 0; i < 8; i++) {
        int grow = row0 + row_g * 8 + i;
        if (grow < N_NODES) {
            float4 o0 = {acc[i][0], acc[i][1], acc[i][2], acc[i][3]};
            float4 o1 = {acc[i][4], acc[i][5], acc[i][6], acc[i][7]};
            *(float4*)&g_h[grow * HID + c0]     = o0;
            *(float4*)&g_h[grow * HID + c0 + 4] = o1;
        }
    }
}

// ---------------- gather aggregate: zin[n] = h[n] + sum_e relu(h[src] + ea@W + b) ----------------
// one warp per node (grid-strided); lane owns 4 channels; W in registers (shfl-broadcast proj)
__global__ void aggregate_kernel(const float* __restrict__ ea,
                                 const float* __restrict__ W,
                                 const float* __restrict__ b) {
    const int lane = threadIdx.x & 31;
    const int gw = (blockIdx.x * blockDim.x + threadIdx.x) >> 5;
    const int nw = (gridDim.x * blockDim.x) >> 5;
    const int c0 = lane * 4;

    float4 w[EDGE_DIM];
#pragma unroll
    for (int k = 0; k < EDGE_DIM; k++) w[k] = *(const float4*)&W[k * HID + c0];
    const float4 bias = *(const float4*)&b[c0];

    for (int n = gw; n < N_NODES; n += nw) {
        const int start = g_off[n];
        const int end   = g_off[n + 1];

        float4 acc = *(const float4*)&g_h[(size_t)n * HID + c0];  // z = h + agg

        for (int base = start; base < end; base += 32) {
            const int take = min(32, end - base);
            int2 ent = make_int2(0, 0);
            if (lane < take) ent = g_csr[base + lane];

            // prefetch edge 0
            int s0 = __shfl_sync(FULLMASK, ent.x, 0);
            int e0 = __shfl_sync(FULLMASK, ent.y, 0);
            float4 hv = *(const float4*)&g_h[(size_t)s0 * HID + c0];
            float eav = (lane < EDGE_DIM) ? __ldg(&ea[(size_t)e0 * EDGE_DIM + lane]) : 0.f;

            for (int j = 0; j < take; j++) {
                float4 hv_c = hv;
                float eav_c = eav;
                if (j + 1 < take) {
                    int s1 = __shfl_sync(FULLMASK, ent.x, j + 1);
                    int e1 = __shfl_sync(FULLMASK, ent.y, j + 1);
                    hv = *(const float4*)&g_h[(size_t)s1 * HID + c0];
                    eav = (lane < EDGE_DIM) ? __ldg(&ea[(size_t)e1 * EDGE_DIM + lane]) : 0.f;
                }
                float4 p = bias;
#pragma unroll
                for (int k = 0; k < EDGE_DIM; k++) {
                    float a = __shfl_sync(FULLMASK, eav_c, k);
                    p.x = fmaf(a, w[k].x, p.x);
                    p.y = fmaf(a, w[k].y, p.y);
                    p.z = fmaf(a, w[k].z, p.z);
                    p.w = fmaf(a, w[k].w, p.w);
                }
                acc.x += fmaxf(hv_c.x + p.x, 0.f);
                acc.y += fmaxf(hv_c.y + p.y, 0.f);
                acc.z += fmaxf(hv_c.z + p.z, 0.f);
                acc.w += fmaxf(hv_c.w + p.w, 0.f);
            }
        }
        *(float4*)&g_zin[(size_t)n * HID + c0] = acc;
    }
}

// ---------------- fused node MLP + BN-stats epilogue ----------------
// 256 threads, 128 rows/block, 8x8 microtile; smem: W1 64KB + W2 64KB + A/T 64KB
__global__ void mlp_kernel(const float* __restrict__ W1, const float* __restrict__ b1,
                           const float* __restrict__ W2, const float* __restrict__ b2,
                           int layer) {
    extern __shared__ float sm[];
    float* sW1 = sm;                   // reused for stats after GEMM1
    float* sW2 = sm + HID * HID;
    float* sA  = sm + 2 * HID * HID;   // [128][128], reused for T
    const int tid = threadIdx.x;       // 256
    const int row0 = blockIdx.x * 128;

    for (int i = tid; i < HID * HID / 4; i += 256) {
        ((float4*)sW1)[i] = ((const float4*)W1)[i];
        ((float4*)sW2)[i] = ((const float4*)W2)[i];
    }
    for (int i = tid; i < 128 * HID / 4; i += 256) {
        int r  = i >> 5;
        int grow = row0 + r;
        float4 v = {0.f, 0.f, 0.f, 0.f};
        if (grow < N_NODES) v = ((const float4*)g_zin)[i + row0 * 32];
        ((float4*)sA)[i] = v;
    }
    __syncthreads();

    const int col_g = tid & 15;
    const int row_g = tid >> 4;
    const int c0 = col_g * 8;
    const int r0 = row_g * 8;
    float acc[8][8];

    // ---- GEMM1 ----
    {
        float4 b0 = *(const float4*)&b1[c0];
        float4 b1v = *(const float4*)&b1[c0 + 4];
#pragma unroll
        for (int i = 0; i < 8; i++) {
            acc[i][0] = b0.x; acc[i][1] = b0.y; acc[i][2] = b0.z; acc[i][3] = b0.w;
            acc[i][4] = b1v.x; acc[i][5] = b1v.y; acc[i][6] = b1v.z; acc[i][7] = b1v.w;
        }
    }
#pragma unroll 1
    for (int k0 = 0; k0 < HID; k0 += 4) {
        float4 av[8];
#pragma unroll
        for (int i = 0; i < 8; i++)
            av[i] = *(const float4*)&sA[(r0 + i) * HID + k0];
#pragma unroll
        for (int kk = 0; kk < 4; kk++) {
            float4 w0 = *(const float4*)&sW1[(k0 + kk) * HID + c0];
            float4 w1 = *(const float4*)&sW1[(k0 + kk) * HID + c0 + 4];
#pragma unroll
            for (int i = 0; i < 8; i++) {
                float a = ((const float*)&av[i])[kk];
                acc[i][0] = fmaf(a, w0.x, acc[i][0]);
                acc[i][1] = fmaf(a, w0.y, acc[i][1]);
                acc[i][2] = fmaf(a, w0.z, acc[i][2]);
                acc[i][3] = fmaf(a, w0.w, acc[i][3]);
                acc[i][4] = fmaf(a, w1.x, acc[i][4]);
                acc[i][5] = fmaf(a, w1.y, acc[i][5]);
                acc[i][6] = fmaf(a, w1.z, acc[i][6]);
                acc[i][7] = fmaf(a, w1.w, acc[i][7]);
            }
        }
    }
    __syncthreads();
    // write T = relu(acc) into sA; zero stats region in sW1
#pragma unroll
    for (int i = 0; i < 8; i++) {
        float4 o0 = {fmaxf(acc[i][0], 0.f), fmaxf(acc[i][1], 0.f),
                     fmaxf(acc[i][2], 0.f), fmaxf(acc[i][3], 0.f)};
        float4 o1 = {fmaxf(acc[i][4], 0.f), fmaxf(acc[i][5], 0.f),
                     fmaxf(acc[i][6], 0.f), fmaxf(acc[i][7], 0.f)};
        *(float4*)&sA[(r0 + i) * HID + c0]     = o0;
        *(float4*)&sA[(r0 + i) * HID + c0 + 4] = o1;
    }
    if (tid < 2 * HID) sW1[tid] = 0.f;
    __syncthreads();

    // ---- GEMM2 ----
    {
        float4 b0 = *(const float4*)&b2[c0];
        float4 b1v = *(const float4*)&b2[c0 + 4];
#pragma unroll
        for (int i = 0; i < 8; i++) {
            acc[i][0] = b0.x; acc[i][1] = b0.y; acc[i][2] = b0.z; acc[i][3] = b0.w;
            acc[i][4] = b1v.x; acc[i][5] = b1v.y; acc[i][6] = b1v.z; acc[i][7] = b1v.w;
        }
    }
#pragma unroll 1
    for (int k0 = 0; k0 < HID; k0 += 4) {
        float4 av[8];
#pragma unroll
        for (int i = 0; i < 8; i++)
            av[i] = *(const float4*)&sA[(r0 + i) * HID + k0];
#pragma unroll
        for (int kk = 0; kk < 4; kk++) {
            float4 w0 = *(const float4*)&sW2[(k0 + kk) * HID + c0];
            float4 w1 = *(const float4*)&sW2[(k0 + kk) * HID + c0 + 4];
#pragma unroll
            for (int i = 0; i < 8; i++) {
                float a = ((const float*)&av[i])[kk];
                acc[i][0] = fmaf(a, w0.x, acc[i][0]);
                acc[i][1] = fmaf(a, w0.y, acc[i][1]);
                acc[i][2] = fmaf(a, w0.z, acc[i][2]);
                acc[i][3] = fmaf(a, w0.w, acc[i][3]);
                acc[i][4] = fmaf(a, w1.x, acc[i][4]);
                acc[i][5] = fmaf(a, w1.y, acc[i][5]);
                acc[i][6] = fmaf(a, w1.z, acc[i][6]);
                acc[i][7] = fmaf(a, w1.w, acc[i][7]);
            }
        }
    }
    // write z + accumulate per-block BN stats
    float s[8], sq[8];
#pragma unroll
    for (int j = 0; j < 8; j++) { s[j] = 0.f; sq[j] = 0.f; }
#pragma unroll
    for (int i = 0; i < 8; i++) {
        int grow = row0 + r0 + i;
        if (grow < N_NODES) {
            float4 o0 = {acc[i][0], acc[i][1], acc[i][2], acc[i][3]};
            float4 o1 = {acc[i][4], acc[i][5], acc[i][6], acc[i][7]};
            *(float4*)&g_z[grow * HID + c0]     = o0;
            *(float4*)&g_z[grow * HID + c0 + 4] = o1;
#pragma unroll
            for (int j = 0; j < 8; j++) {
                s[j] += acc[i][j];
                sq[j] = fmaf(acc[i][j], acc[i][j], sq[j]);
            }
        }
    }
#pragma unroll
    for (int j = 0; j < 8; j++) {
        atomicAdd(&sW1[c0 + j], s[j]);
        atomicAdd(&sW1[HID + c0 + j], sq[j]);
    }
    __syncthreads();
    if (tid < 2 * HID)
        atomicAdd(&g_stats[layer * 2 * HID + tid], sW1[tid]);
}

// ---------------- BN apply + relu ----------------
__global__ void bn_apply_kernel(const float* __restrict__ gamma,
                                const float* __restrict__ beta,
                                int layer) {
    const int i0 = blockIdx.x * blockDim.x + threadIdx.x;
    const int stride = gridDim.x * blockDim.x;
    const int c4 = (i0 & 31) * 4;
    const float* st = &g_stats[layer * 2 * HID];
    const float inv_n = 1.f / (float)N_NODES;
    float sc[4], sh[4];
#pragma unroll
    for (int j = 0; j < 4; j++) {
        float mean = st[c4 + j] * inv_n;
        float var  = st[HID + c4 + j] * inv_n - mean * mean;
        sc[j] = gamma[c4 + j] * rsqrtf(var + BN_EPS);
        sh[j] = beta[c4 + j] - mean * sc[j];
    }
    for (int i = i0; i < N_NODES * HID / 4; i += stride) {
        float4 z = ((const float4*)g_z)[i];
        float4 o;
        o.x = fmaxf(fmaf(z.x, sc[0], sh[0]), 0.f);
        o.y = fmaxf(fmaf(z.y, sc[1], sh[1]), 0.f);
        o.z = fmaxf(fmaf(z.z, sc[2], sh[2]), 0.f);
        o.w = fmaxf(fmaf(z.w, sc[3], sh[3]), 0.f);
        ((float4*)g_h)[i] = o;
    }
}

// ---------------- global_add_pool over sorted batch ----------------
__global__ void pool_kernel(const int* __restrict__ batch) {
    const int c = threadIdx.x;  // 128
    const int row0 = blockIdx.x * 256;
    if (row0 >= N_NODES) return;
    const int rowEnd = min(row0 + 256, N_NODES);
    float acc = 0.f;
    int cur = batch[row0];
    for (int row = row0; row < rowEnd; row++) {
        int bv = batch[row];
        if (bv != cur) {
            atomicAdd(&g_pool[cur * HID + c], acc);
            acc = 0.f;
            cur = bv;
        }
        acc += g_h[row * HID + c];
    }
    atomicAdd(&g_pool[cur * HID + c], acc);
}

// ---------------- head ----------------
__global__ void head_kernel(const float* __restrict__ W1, const float* __restrict__ b1,
                            const float* __restrict__ W2, const float* __restrict__ b2,
                            float* __restrict__ out) {
    extern __shared__ float sm[];
    float* sG = sm;                    // [64][128]
    float* sW = sm + NUM_GRAPHS * HID; // [128][128]
    const int tid = threadIdx.x;  // 256

    for (int i = tid; i < NUM_GRAPHS * HID / 4; i += 256)
        ((float4*)sG)[i] = ((const float4*)g_pool)[i];
    for (int i = tid; i < HID * HID / 4; i += 256)
        ((float4*)sW)[i] = ((const float4*)W1)[i];
    __syncthreads();

    const int c  = tid & 127;
    const int r0 = (tid >> 7) * 32;
    float t[32];
    float bc = b1[c];
#pragma unroll
    for (int i = 0; i < 32; i++) t[i] = bc;
    for (int k = 0; k < HID; k++) {
        float wv = sW[k * HID + c];
#pragma unroll 8
        for (int i = 0; i < 32; i++)
            t[i] = fmaf(sG[(r0 + i) * HID + k], wv, t[i]);
    }
    __syncthreads();
#pragma unroll
    for (int i = 0; i < 32; i++)
        sG[(r0 + i) * HID + c] = fmaxf(t[i], 0.f);
    __syncthreads();

    if (tid < NUM_GRAPHS * N_CLASSES) {
        int r  = tid / N_CLASSES;
        int cc = tid % N_CLASSES;
        float accv = b2[cc];
        for (int k = 0; k < HID; k++)
            accv = fmaf(sG[r * HID + k], W2[k * N_CLASSES + cc], accv);
        out[tid] = accv;
    }
}

// ---------------- launch ----------------
extern "C" void kernel_launch(void* const* d_in, const int* in_sizes, int n_in,
                              void* d_out, int out_size) {
    const float* x      = (const float*)d_in[0];
    const int*   ei     = (const int*)d_in[1];
    const float* ea     = (const float*)d_in[2];
    const int*   batch  = (const int*)d_in[3];
    const float* enc_W  = (const float*)d_in[4];
    const float* enc_b  = (const float*)d_in[5];
    const float* edge_W = (const float*)d_in[6];
    const float* edge_b = (const float*)d_in[7];
    const float* mlp_W1 = (const float*)d_in[8];
    const float* mlp_b1 = (const float*)d_in[9];
    const float* mlp_W2 = (const float*)d_in[10];
    const float* mlp_b2 = (const float*)d_in[11];
    const float* bn_g   = (const float*)d_in[12];
    const float* bn_b   = (const float*)d_in[13];
    const float* hW1    = (const float*)d_in[14];
    const float* hb1    = (const float*)d_in[15];
    const float* hW2    = (const float*)d_in[16];
    const float* hb2    = (const float*)d_in[17];
    float* out = (float*)d_out;

    cudaFuncSetAttribute(enc_kernel,  cudaFuncAttributeMaxDynamicSharedMemorySize, 64 * 1024);
    cudaFuncSetAttribute(mlp_kernel,  cudaFuncAttributeMaxDynamicSharedMemorySize, 192 * 1024);
    cudaFuncSetAttribute(head_kernel, cudaFuncAttributeMaxDynamicSharedMemorySize, 96 * 1024);

    const int row_blocks = (N_NODES + 127) / 128;  // 391

    zero_init_kernel<<<256, 256>>>();
    csr_hist_kernel<<<(N_EDGES + 255) / 256, 256>>>(ei);
    csr_scan_kernel<<<1, 1024>>>();
    csr_scatter_kernel<<<(N_EDGES + 255) / 256, 256>>>(ei);

    enc_kernel<<<row_blocks, 256, 64 * 1024>>>(x, enc_W, enc_b);

    for (int l = 0; l < N_LAYERS; l++) {
        aggregate_kernel<<<1563, 256>>>(ea,
                                        edge_W + (size_t)l * EDGE_DIM * HID,
                                        edge_b + (size_t)l * HID);
        mlp_kernel<<<row_blocks, 256, 192 * 1024>>>(
            mlp_W1 + (size_t)l * HID * HID, mlp_b1 + (size_t)l * HID,
            mlp_W2 + (size_t)l * HID * HID, mlp_b2 + (size_t)l * HID, l);
        bn_apply_kernel<<<2048, 256>>>(bn_g + (size_t)l * HID,
                                       bn_b + (size_t)l * HID, l);
    }

    pool_kernel<<<(N_NODES + 255) / 256, 128>>>(batch);
    head_kernel<<<1, 256, 96 * 1024>>>(hW1, hb1, hW2, hb2, out);
}

// round 4
// speedup vs baseline: 1.3573x; 1.1621x over previous
#include <cuda_runtime.h>
#include <cuda_bf16.h>

#define N_NODES   50000
#define N_EDGES   640000
#define F_IN      64
#define EDGE_DIM  16
#define HID       128
#define N_LAYERS  3
#define NUM_GRAPHS 64
#define N_CLASSES 2
#define BN_EPS    1e-5f
#define FULLMASK  0xffffffffu

// ---------------- packed fp32x2 FMA (Blackwell; exact fp32 numerics) ----------------
__device__ __forceinline__ float2 ffma2(float2 a, float2 b, float2 c) {
    float2 d;
    asm("fma.rn.f32x2 %0, %1, %2, %3;"
        : "=l"(reinterpret_cast<unsigned long long&>(d))
        : "l"(reinterpret_cast<unsigned long long&>(a)),
          "l"(reinterpret_cast<unsigned long long&>(b)),
          "l"(reinterpret_cast<unsigned long long&>(c)));
    return d;
}

// ---------------- scratch ----------------
__device__ float g_h[N_NODES * HID];      // node features (post-BN)
__device__ float g_zin[N_NODES * HID];    // h + aggregated messages (MLP input)
__device__ float g_z[N_NODES * HID];      // MLP output pre-BN
__device__ float g_stats[N_LAYERS * 2 * HID];
__device__ float g_pool[NUM_GRAPHS * HID];
__device__ int   g_deg[N_NODES];
__device__ int   g_off[N_NODES + 1];
__device__ int   g_pos[N_NODES];
__device__ int   g_src[N_EDGES];                   // src sorted by dst
__device__ float g_ea_s[N_EDGES * EDGE_DIM];       // edge_attr sorted by dst

// ---------------- init ----------------
__global__ void zero_init_kernel() {
    int i = blockIdx.x * blockDim.x + threadIdx.x;
    int stride = gridDim.x * blockDim.x;
    for (int j = i; j < N_NODES; j += stride) g_deg[j] = 0;
    if (i < N_LAYERS * 2 * HID) g_stats[i] = 0.f;
    if (i < NUM_GRAPHS * HID) g_pool[i] = 0.f;
}

// ---------------- CSR build ----------------
__global__ void csr_hist_kernel(const int* __restrict__ ei) {
    int e = blockIdx.x * blockDim.x + threadIdx.x;
    if (e < N_EDGES) atomicAdd(&g_deg[ei[N_EDGES + e]], 1);
}

__global__ void csr_scan_kernel() {   // 1 block, 1024 threads
    __shared__ int part[1024];
    const int T = 1024;
    const int C = (N_NODES + T - 1) / T;
    int t = threadIdx.x;
    int lo = t * C, hi = min(lo + C, N_NODES);
    int s = 0;
    for (int i = lo; i < hi; i++) s += g_deg[i];
    part[t] = s;
    __syncthreads();
    for (int d = 1; d < T; d <<= 1) {
        int v = (t >= d) ? part[t - d] : 0;
        __syncthreads();
        part[t] += v;
        __syncthreads();
    }
    int run = (t > 0) ? part[t - 1] : 0;
    for (int i = lo; i < hi; i++) {
        g_off[i] = run;
        g_pos[i] = run;
        run += g_deg[i];
    }
    if (t == T - 1) g_off[N_NODES] = run;
}

__global__ void csr_scatter_kernel(const int* __restrict__ ei,
                                   const float* __restrict__ ea) {
    int e = blockIdx.x * blockDim.x + threadIdx.x;
    if (e < N_EDGES) {
        int s = ei[e];
        int d = ei[N_EDGES + e];
        int p = atomicAdd(&g_pos[d], 1);
        g_src[p] = s;
        const float4* sp = (const float4*)&ea[(size_t)e * EDGE_DIM];
        float4* dp = (float4*)&g_ea_s[(size_t)p * EDGE_DIM];
        dp[0] = sp[0]; dp[1] = sp[1]; dp[2] = sp[2]; dp[3] = sp[3];
    }
}

// ---------------- encoder: h = x @ enc_W + enc_b (FFMA2 channel pairs) ----------------
__global__ void enc_kernel(const float* __restrict__ x,
                           const float* __restrict__ W,
                           const float* __restrict__ b) {
    extern __shared__ float sm[];
    float* sW = sm;               // [64][128]
    float* sA = sm + F_IN * HID;  // [128][64]
    const int tid = threadIdx.x;
    const int row0 = blockIdx.x * 128;

    for (int i = tid; i < F_IN * HID / 4; i += 256)
        ((float4*)sW)[i] = ((const float4*)W)[i];
    for (int i = tid; i < 128 * F_IN / 4; i += 256) {
        int r  = i >> 4;
        int k4 = i & 15;
        int grow = row0 + r;
        float4 v = {0.f, 0.f, 0.f, 0.f};
        if (grow < N_NODES) v = ((const float4*)x)[grow * 16 + k4];
        ((float4*)sA)[i] = v;
    }
    __syncthreads();

    const int col_g = tid & 15;
    const int row_g = tid >> 4;
    const int c0 = col_g * 8;

    float2 acc2[8][4];
    {
        float4 b0 = *(const float4*)&b[c0];
        float4 b1 = *(const float4*)&b[c0 + 4];
#pragma unroll
        for (int i = 0; i < 8; i++) {
            acc2[i][0] = make_float2(b0.x, b0.y);
            acc2[i][1] = make_float2(b0.z, b0.w);
            acc2[i][2] = make_float2(b1.x, b1.y);
            acc2[i][3] = make_float2(b1.z, b1.w);
        }
    }
#pragma unroll 1
    for (int k0 = 0; k0 < F_IN; k0 += 4) {
        float4 av[8];
#pragma unroll
        for (int i = 0; i < 8; i++)
            av[i] = *(const float4*)&sA[(row_g * 8 + i) * F_IN + k0];
#pragma unroll
        for (int kk = 0; kk < 4; kk++) {
            float4 w0 = *(const float4*)&sW[(k0 + kk) * HID + c0];
            float4 w1 = *(const float4*)&sW[(k0 + kk) * HID + c0 + 4];
            float2 wp0 = make_float2(w0.x, w0.y);
            float2 wp1 = make_float2(w0.z, w0.w);
            float2 wp2 = make_float2(w1.x, w1.y);
            float2 wp3 = make_float2(w1.z, w1.w);
#pragma unroll
            for (int i = 0; i < 8; i++) {
                float a = ((const float*)&av[i])[kk];
                float2 aa = make_float2(a, a);
                acc2[i][0] = ffma2(aa, wp0, acc2[i][0]);
                acc2[i][1] = ffma2(aa, wp1, acc2[i][1]);
                acc2[i][2] = ffma2(aa, wp2, acc2[i][2]);
                acc2[i][3] = ffma2(aa, wp3, acc2[i][3]);
            }
        }
    }
#pragma unroll
    for (int i = 0; i < 8; i++) {
        int grow = row0 + row_g * 8 + i;
        if (grow < N_NODES) {
            float4 o0 = {acc2[i][0].x, acc2[i][0].y, acc2[i][1].x, acc2[i][1].y};
            float4 o1 = {acc2[i][2].x, acc2[i][2].y, acc2[i][3].x, acc2[i][3].y};
            *(float4*)&g_h[grow * HID + c0]     = o0;
            *(float4*)&g_h[grow * HID + c0 + 4] = o1;
        }
    }
}

// ---------------- gather aggregate: zin[n] = h[n] + sum relu(h[src] + ea@W + b) ----------------
// one warp per node; lane owns 4 channels; k-split FFMA2 with smem-staged sorted edge attrs
#define AGG_WARPS 8
__global__ void aggregate_kernel(const float* __restrict__ W,
                                 const float* __restrict__ b) {
    __shared__ float sEA[AGG_WARPS][32 * EDGE_DIM];
    const int lane = threadIdx.x & 31;
    const int wib = threadIdx.x >> 5;
    const int gw = (blockIdx.x * blockDim.x + threadIdx.x) >> 5;
    const int nw = (gridDim.x * blockDim.x) >> 5;
    const int c0 = lane * 4;
    float* myEA = sEA[wib];

    // prepack w2[kp][c] = {W[2kp][c0+c], W[2kp+1][c0+c]}  (k-transposed pairs)
    float2 w2[EDGE_DIM / 2][4];
#pragma unroll
    for (int kp = 0; kp < EDGE_DIM / 2; kp++) {
        float4 wa = *(const float4*)&W[(2 * kp) * HID + c0];
        float4 wb = *(const float4*)&W[(2 * kp + 1) * HID + c0];
        w2[kp][0] = make_float2(wa.x, wb.x);
        w2[kp][1] = make_float2(wa.y, wb.y);
        w2[kp][2] = make_float2(wa.z, wb.z);
        w2[kp][3] = make_float2(wa.w, wb.w);
    }
    const float4 bias = *(const float4*)&b[c0];

    for (int n = gw; n < N_NODES; n += nw) {
        const int start = g_off[n];
        const int end   = g_off[n + 1];
        float4 acc = *(const float4*)&g_h[(size_t)n * HID + c0];

        for (int base = start; base < end; base += 32) {
            const int take = min(32, end - base);
            // stage edge attrs (contiguous in CSR order)
            const float4* src4 = (const float4*)&g_ea_s[(size_t)base * EDGE_DIM];
            for (int t = lane; t < take * 4; t += 32)
                ((float4*)myEA)[t] = src4[t];
            int s = (lane < take) ? g_src[base + lane] : 0;
            __syncwarp();

            int s0 = __shfl_sync(FULLMASK, s, 0);
            float4 hv = *(const float4*)&g_h[(size_t)s0 * HID + c0];

            for (int j = 0; j < take; j++) {
                float4 hv_c = hv;
                if (j + 1 < take) {
                    int s1 = __shfl_sync(FULLMASK, s, j + 1);
                    hv = *(const float4*)&g_h[(size_t)s1 * HID + c0];
                }
                // projection: per-channel {even,odd} partial sums
                float2 e0 = {0.f, 0.f}, e1 = {0.f, 0.f}, e2 = {0.f, 0.f}, e3 = {0.f, 0.f};
#pragma unroll
                for (int kp = 0; kp < EDGE_DIM / 2; kp++) {
                    float2 a2 = *(const float2*)&myEA[j * EDGE_DIM + 2 * kp]; // broadcast LDS.64
                    e0 = ffma2(a2, w2[kp][0], e0);
                    e1 = ffma2(a2, w2[kp][1], e1);
                    e2 = ffma2(a2, w2[kp][2], e2);
                    e3 = ffma2(a2, w2[kp][3], e3);
                }
                acc.x += fmaxf(hv_c.x + bias.x + e0.x + e0.y, 0.f);
                acc.y += fmaxf(hv_c.y + bias.y + e1.x + e1.y, 0.f);
                acc.z += fmaxf(hv_c.z + bias.z + e2.x + e2.y, 0.f);
                acc.w += fmaxf(hv_c.w + bias.w + e3.x + e3.y, 0.f);
            }
            __syncwarp();
        }
        *(float4*)&g_zin[(size_t)n * HID + c0] = acc;
    }
}

// ---------------- fused node MLP + BN-stats epilogue (FFMA2 channel pairs) ----------------
__global__ void __launch_bounds__(256) mlp_kernel(
        const float* __restrict__ W1, const float* __restrict__ b1,
        const float* __restrict__ W2, const float* __restrict__ b2,
        int layer) {
    extern __shared__ float sm[];
    float* sW1 = sm;                   // reused for stats after GEMM1
    float* sW2 = sm + HID * HID;
    float* sA  = sm + 2 * HID * HID;   // [128][128], reused for T
    const int tid = threadIdx.x;       // 256
    const int row0 = blockIdx.x * 128;

    for (int i = tid; i < HID * HID / 4; i += 256) {
        ((float4*)sW1)[i] = ((const float4*)W1)[i];
        ((float4*)sW2)[i] = ((const float4*)W2)[i];
    }
    for (int i = tid; i < 128 * HID / 4; i += 256) {
        int r = i >> 5;
        int grow = row0 + r;
        float4 v = {0.f, 0.f, 0.f, 0.f};
        if (grow < N_NODES) v = ((const float4*)g_zin)[i + row0 * 32];
        ((float4*)sA)[i] = v;
    }
    __syncthreads();

    const int col_g = tid & 15;
    const int row_g = tid >> 4;
    const int c0 = col_g * 8;
    const int r0 = row_g * 8;
    float2 acc2[8][4];

    // ---- GEMM1 ----
    {
        float4 b0 = *(const float4*)&b1[c0];
        float4 b1v = *(const float4*)&b1[c0 + 4];
#pragma unroll
        for (int i = 0; i < 8; i++) {
            acc2[i][0] = make_float2(b0.x, b0.y);
            acc2[i][1] = make_float2(b0.z, b0.w);
            acc2[i][2] = make_float2(b1v.x, b1v.y);
            acc2[i][3] = make_float2(b1v.z, b1v.w);
        }
    }
#pragma unroll 1
    for (int k0 = 0; k0 < HID; k0 += 4) {
        float4 av[8];
#pragma unroll
        for (int i = 0; i < 8; i++)
            av[i] = *(const float4*)&sA[(r0 + i) * HID + k0];
#pragma unroll
        for (int kk = 0; kk < 4; kk++) {
            float4 w0 = *(const float4*)&sW1[(k0 + kk) * HID + c0];
            float4 w1 = *(const float4*)&sW1[(k0 + kk) * HID + c0 + 4];
            float2 wp0 = make_float2(w0.x, w0.y);
            float2 wp1 = make_float2(w0.z, w0.w);
            float2 wp2 = make_float2(w1.x, w1.y);
            float2 wp3 = make_float2(w1.z, w1.w);
#pragma unroll
            for (int i = 0; i < 8; i++) {
                float a = ((const float*)&av[i])[kk];
                float2 aa = make_float2(a, a);
                acc2[i][0] = ffma2(aa, wp0, acc2[i][0]);
                acc2[i][1] = ffma2(aa, wp1, acc2[i][1]);
                acc2[i][2] = ffma2(aa, wp2, acc2[i][2]);
                acc2[i][3] = ffma2(aa, wp3, acc2[i][3]);
            }
        }
    }
    __syncthreads();
    // write T = relu into sA; zero stats region in sW1
#pragma unroll
    for (int i = 0; i < 8; i++) {
        float4 o0 = {fmaxf(acc2[i][0].x, 0.f), fmaxf(acc2[i][0].y, 0.f),
                     fmaxf(acc2[i][1].x, 0.f), fmaxf(acc2[i][1].y, 0.f)};
        float4 o1 = {fmaxf(acc2[i][2].x, 0.f), fmaxf(acc2[i][2].y, 0.f),
                     fmaxf(acc2[i][3].x, 0.f), fmaxf(acc2[i][3].y, 0.f)};
        *(float4*)&sA[(r0 + i) * HID + c0]     = o0;
        *(float4*)&sA[(r0 + i) * HID + c0 + 4] = o1;
    }
    if (tid < 2 * HID) sW1[tid] = 0.f;
    __syncthreads();

    // ---- GEMM2 ----
    {
        float4 b0 = *(const float4*)&b2[c0];
        float4 b1v = *(const float4*)&b2[c0 + 4];
#pragma unroll
        for (int i = 0; i < 8; i++) {
            acc2[i][0] = make_float2(b0.x, b0.y);
            acc2[i][1] = make_float2(b0.z, b0.w);
            acc2[i][2] = make_float2(b1v.x, b1v.y);
            acc2[i][3] = make_float2(b1v.z, b1v.w);
        }
    }
#pragma unroll 1
    for (int k0 = 0; k0 < HID; k0 += 4) {
        float4 av[8];
#pragma unroll
        for (int i = 0; i < 8; i++)
            av[i] = *(const float4*)&sA[(r0 + i) * HID + k0];
#pragma unroll
        for (int kk = 0; kk < 4; kk++) {
            float4 w0 = *(const float4*)&sW2[(k0 + kk) * HID + c0];
            float4 w1 = *(const float4*)&sW2[(k0 + kk) * HID + c0 + 4];
            float2 wp0 = make_float2(w0.x, w0.y);
            float2 wp1 = make_float2(w0.z, w0.w);
            float2 wp2 = make_float2(w1.x, w1.y);
            float2 wp3 = make_float2(w1.z, w1.w);
#pragma unroll
            for (int i = 0; i < 8; i++) {
                float a = ((const float*)&av[i])[kk];
                float2 aa = make_float2(a, a);
                acc2[i][0] = ffma2(aa, wp0, acc2[i][0]);
                acc2[i][1] = ffma2(aa, wp1, acc2[i][1]);
                acc2[i][2] = ffma2(aa, wp2, acc2[i][2]);
                acc2[i][3] = ffma2(aa, wp3, acc2[i][3]);
            }
        }
    }
    // write z + per-block BN stats
    float s[8], sq[8];
#pragma unroll
    for (int j = 0; j < 8; j++) { s[j] = 0.f; sq[j] = 0.f; }
#pragma unroll
    for (int i = 0; i < 8; i++) {
        int grow = row0 + r0 + i;
        if (grow < N_NODES) {
            float v[8] = {acc2[i][0].x, acc2[i][0].y, acc2[i][1].x, acc2[i][1].y,
                          acc2[i][2].x, acc2[i][2].y, acc2[i][3].x, acc2[i][3].y};
            float4 o0 = {v[0], v[1], v[2], v[3]};
            float4 o1 = {v[4], v[5], v[6], v[7]};
            *(float4*)&g_z[grow * HID + c0]     = o0;
            *(float4*)&g_z[grow * HID + c0 + 4] = o1;
#pragma unroll
            for (int j = 0; j < 8; j++) {
                s[j] += v[j];
                sq[j] = fmaf(v[j], v[j], sq[j]);
            }
        }
    }
#pragma unroll
    for (int j = 0; j < 8; j++) {
        atomicAdd(&sW1[c0 + j], s[j]);
        atomicAdd(&sW1[HID + c0 + j], sq[j]);
    }
    __syncthreads();
    if (tid < 2 * HID)
        atomicAdd(&g_stats[layer * 2 * HID + tid], sW1[tid]);
}

// ---------------- BN apply + relu ----------------
__global__ void bn_apply_kernel(const float* __restrict__ gamma,
                                const float* __restrict__ beta,
                                int layer) {
    const int i0 = blockIdx.x * blockDim.x + threadIdx.x;
    const int stride = gridDim.x * blockDim.x;
    const int c4 = (i0 & 31) * 4;
    const float* st = &g_stats[layer * 2 * HID];
    const float inv_n = 1.f / (float)N_NODES;
    float sc[4], sh[4];
#pragma unroll
    for (int j = 0; j < 4; j++) {
        float mean = st[c4 + j] * inv_n;
        float var  = st[HID + c4 + j] * inv_n - mean * mean;
        sc[j] = gamma[c4 + j] * rsqrtf(var + BN_EPS);
        sh[j] = beta[c4 + j] - mean * sc[j];
    }
    for (int i = i0; i < N_NODES * HID / 4; i += stride) {
        float4 z = ((const float4*)g_z)[i];
        float4 o;
        o.x = fmaxf(fmaf(z.x, sc[0], sh[0]), 0.f);
        o.y = fmaxf(fmaf(z.y, sc[1], sh[1]), 0.f);
        o.z = fmaxf(fmaf(z.z, sc[2], sh[2]), 0.f);
        o.w = fmaxf(fmaf(z.w, sc[3], sh[3]), 0.f);
        ((float4*)g_h)[i] = o;
    }
}

// ---------------- global_add_pool over sorted batch ----------------
__global__ void pool_kernel(const int* __restrict__ batch) {
    const int c = threadIdx.x;  // 128
    const int row0 = blockIdx.x * 256;
    if (row0 >= N_NODES) return;
    const int rowEnd = min(row0 + 256, N_NODES);
    float acc = 0.f;
    int cur = batch[row0];
    for (int row = row0; row < rowEnd; row++) {
        int bv = batch[row];
        if (bv != cur) {
            atomicAdd(&g_pool[cur * HID + c], acc);
            acc = 0.f;
            cur = bv;
        }
        acc += g_h[row * HID + c];
    }
    atomicAdd(&g_pool[cur * HID + c], acc);
}

// ---------------- head ----------------
__global__ void head_kernel(const float* __restrict__ W1, const float* __restrict__ b1,
                            const float* __restrict__ W2, const float* __restrict__ b2,
                            float* __restrict__ out) {
    extern __shared__ float sm[];
    float* sG = sm;                    // [64][128]
    float* sW = sm + NUM_GRAPHS * HID; // [128][128]
    const int tid = threadIdx.x;  // 256

    for (int i = tid; i < NUM_GRAPHS * HID / 4; i += 256)
        ((float4*)sG)[i] = ((const float4*)g_pool)[i];
    for (int i = tid; i < HID * HID / 4; i += 256)
        ((float4*)sW)[i] = ((const float4*)W1)[i];
    __syncthreads();

    const int c  = tid & 127;
    const int r0 = (tid >> 7) * 32;
    float t[32];
    float bc = b1[c];
#pragma unroll
    for (int i = 0; i < 32; i++) t[i] = bc;
    for (int k = 0; k < HID; k++) {
        float wv = sW[k * HID + c];
#pragma unroll 8
        for (int i = 0; i < 32; i++)
            t[i] = fmaf(sG[(r0 + i) * HID + k], wv, t[i]);
    }
    __syncthreads();
#pragma unroll
    for (int i = 0; i < 32; i++)
        sG[(r0 + i) * HID + c] = fmaxf(t[i], 0.f);
    __syncthreads();

    if (tid < NUM_GRAPHS * N_CLASSES) {
        int r  = tid / N_CLASSES;
        int cc = tid % N_CLASSES;
        float accv = b2[cc];
        for (int k = 0; k < HID; k++)
            accv = fmaf(sG[r * HID + k], W2[k * N_CLASSES + cc], accv);
        out[tid] = accv;
    }
}

// ---------------- launch ----------------
extern "C" void kernel_launch(void* const* d_in, const int* in_sizes, int n_in,
                              void* d_out, int out_size) {
    const float* x      = (const float*)d_in[0];
    const int*   ei     = (const int*)d_in[1];
    const float* ea     = (const float*)d_in[2];
    const int*   batch  = (const int*)d_in[3];
    const float* enc_W  = (const float*)d_in[4];
    const float* enc_b  = (const float*)d_in[5];
    const float* edge_W = (const float*)d_in[6];
    const float* edge_b = (const float*)d_in[7];
    const float* mlp_W1 = (const float*)d_in[8];
    const float* mlp_b1 = (const float*)d_in[9];
    const float* mlp_W2 = (const float*)d_in[10];
    const float* mlp_b2 = (const float*)d_in[11];
    const float* bn_g   = (const float*)d_in[12];
    const float* bn_b   = (const float*)d_in[13];
    const float* hW1    = (const float*)d_in[14];
    const float* hb1    = (const float*)d_in[15];
    const float* hW2    = (const float*)d_in[16];
    const float* hb2    = (const float*)d_in[17];
    float* out = (float*)d_out;

    cudaFuncSetAttribute(enc_kernel,  cudaFuncAttributeMaxDynamicSharedMemorySize, 64 * 1024);
    cudaFuncSetAttribute(mlp_kernel,  cudaFuncAttributeMaxDynamicSharedMemorySize, 192 * 1024);
    cudaFuncSetAttribute(head_kernel, cudaFuncAttributeMaxDynamicSharedMemorySize, 96 * 1024);

    const int row_blocks = (N_NODES + 127) / 128;  // 391

    zero_init_kernel<<<256, 256>>>();
    csr_hist_kernel<<<(N_EDGES + 255) / 256, 256>>>(ei);
    csr_scan_kernel<<<1, 1024>>>();
    csr_scatter_kernel<<<(N_EDGES + 255) / 256, 256>>>(ei, ea);

    enc_kernel<<<row_blocks, 256, 64 * 1024>>>(x, enc_W, enc_b);

    for (int l = 0; l < N_LAYERS; l++) {
        aggregate_kernel<<<1563, 256>>>(edge_W + (size_t)l * EDGE_DIM * HID,
                                        edge_b + (size_t)l * HID);
        mlp_kernel<<<row_blocks, 256, 192 * 1024>>>(
            mlp_W1 + (size_t)l * HID * HID, mlp_b1 + (size_t)l * HID,
            mlp_W2 + (size_t)l * HID * HID, mlp_b2 + (size_t)l * HID, l);
        bn_apply_kernel<<<2048, 256>>>(bn_g + (size_t)l * HID,
                                       bn_b + (size_t)l * HID, l);
    }

    pool_kernel<<<(N_NODES + 255) / 256, 128>>>(batch);
    head_kernel<<<1, 256, 96 * 1024>>>(hW1, hb1, hW2, hb2, out);
}